// round 9
// baseline (speedup 1.0000x reference)
#include <cuda_runtime.h>
#include <cuda_bf16.h>
#include <cstdint>

// Problem constants
#define NN   10000
#define INF  10000
#define HID  128
#define EMAX 320000

// ---------------- scratch (device globals; no allocation allowed) ----------------
__device__ float g_h[(size_t)NN * HID];                  // h = x @ W_conv
__device__ __align__(16) float g_wt[(size_t)HID * INF];  // W^T [128][10000] (n-major)
__device__ float g_deg[NN];
__device__ float g_dinv[NN];
__device__ int   g_cnt[NN];
__device__ int   g_base[NN + 1];
__device__ int   g_cursor[NN];
__device__ int   g_sr[EMAX];
__device__ float g_sw[EMAX];
__device__ int   g_is32 = 0;   // sticky dtype flag: 1 => edge_index is int32

// ---------------- helpers ----------------
__device__ __forceinline__ unsigned smem_u32(const void* p) {
    unsigned a;
    asm("{ .reg .u64 t; cvta.to.shared.u64 t, %1; cvt.u32.u64 %0, t; }" : "=r"(a) : "l"(p));
    return a;
}

__device__ __forceinline__ void cp_async16(unsigned saddr, const void* gmem_src, int valid_bytes) {
    asm volatile("cp.async.cg.shared.global [%0], [%1], 16, %2;\n"
                 :: "r"(saddr), "l"(gmem_src), "r"(valid_bytes));
}

__device__ __forceinline__ int load_edge_idx(const void* ei, int is32, long long pos) {
    if (is32) return ((const int*)ei)[pos];
    return (int)((const long long*)ei)[pos];
}

__device__ __forceinline__ void ldsm4(unsigned r[4], unsigned saddr) {
    asm volatile("ldmatrix.sync.aligned.m8n8.x4.shared.b16 {%0,%1,%2,%3}, [%4];"
                 : "=r"(r[0]), "=r"(r[1]), "=r"(r[2]), "=r"(r[3]) : "r"(saddr));
}

__device__ __forceinline__ void mma_tf32(float c[4], const unsigned a[4], const unsigned b0, const unsigned b1) {
    asm volatile(
        "mma.sync.aligned.m16n8k8.row.col.f32.tf32.tf32.f32 "
        "{%0,%1,%2,%3}, {%4,%5,%6,%7}, {%8,%9}, {%0,%1,%2,%3};\n"
        : "+f"(c[0]), "+f"(c[1]), "+f"(c[2]), "+f"(c[3])
        : "r"(a[0]), "r"(a[1]), "r"(a[2]), "r"(a[3]), "r"(b0), "r"(b1));
}

// ---------------- kernel 1: init + dtype detect (fused) ----------------
__global__ void k_pre0(const int* __restrict__ ei_words, int E) {
    int i = blockIdx.x * blockDim.x + threadIdx.x;
    if (i < NN) {
        g_deg[i] = 1.0f;     // self-loop weight
        g_cnt[i] = 0;
        g_cursor[i] = 0;
    }
    long long idx = 2LL * i + 1;           // odd 32-bit words: zero iff int64
    if (idx < 2LL * E) {
        if (ei_words[idx] != 0) g_is32 = 1;
    }
}

// ---------------- kernel 2: degree + count ----------------
__global__ void k_count(const void* __restrict__ ei, const float* __restrict__ ew, int E) {
    int e = blockIdx.x * blockDim.x + threadIdx.x;
    if (e >= E) return;
    int is32 = g_is32;
    int c = load_edge_idx(ei, is32, (long long)E + e);
    atomicAdd(&g_deg[c], ew[e]);
    atomicAdd(&g_cnt[c], 1);
}

// ---------------- kernel 3: dinv + exclusive scan (single block, 1024 thr) ----------------
__global__ void k_scan() {
    const int PER = 10;
    int t = threadIdx.x;
    int lane = t & 31, w = t >> 5;
#pragma unroll
    for (int p = 0; p < PER; ++p) {
        int idx = t * PER + p;
        if (idx < NN) {
            float d = g_deg[idx];
            g_dinv[idx] = (d > 0.f) ? rsqrtf(d) : 0.f;
        }
    }
    int local[PER];
    int sum = 0;
#pragma unroll
    for (int p = 0; p < PER; ++p) {
        int idx = t * PER + p;
        int v = (idx < NN) ? g_cnt[idx] : 0;
        local[p] = sum;
        sum += v;
    }
    int x = sum;
#pragma unroll
    for (int o = 1; o < 32; o <<= 1) {
        int y = __shfl_up_sync(0xFFFFFFFFu, x, o);
        if (lane >= o) x += y;
    }
    __shared__ int ws[32];
    if (lane == 31) ws[w] = x;
    __syncthreads();
    if (w == 0) {
        int v = ws[lane];
#pragma unroll
        for (int o = 1; o < 32; o <<= 1) {
            int y = __shfl_up_sync(0xFFFFFFFFu, v, o);
            if (lane >= o) v += y;
        }
        ws[lane] = v;
    }
    __syncthreads();
    int base = (x - sum) + (w > 0 ? ws[w - 1] : 0);
#pragma unroll
    for (int p = 0; p < PER; ++p) {
        int idx = t * PER + p;
        if (idx <= NN) g_base[idx] = base + local[p];
    }
}

// ---------------- kernel 4: fill CSR buckets ----------------
__global__ void k_fill(const void* __restrict__ ei, const float* __restrict__ ew, int E) {
    int e = blockIdx.x * blockDim.x + threadIdx.x;
    if (e >= E) return;
    int is32 = g_is32;
    int r = load_edge_idx(ei, is32, e);
    int c = load_edge_idx(ei, is32, (long long)E + e);
    float wv = ew[e] * g_dinv[r] * g_dinv[c];
    int pos = atomicAdd(&g_cursor[c], 1);
    g_sr[g_base[c] + pos] = r;
    g_sw[g_base[c] + pos] = wv;
}

// ---------------- kernel 5: W transpose  W[K][128] -> WT[128][K] ----------------
__global__ void k_transpose(const float* __restrict__ W) {
    __shared__ float t[32][33];
    int k0 = blockIdx.x * 32, n0 = blockIdx.y * 32;
    int tx = threadIdx.x, ty = threadIdx.y;
    int k = k0 + ty, n = n0 + tx;
    t[ty][tx] = (k < INF) ? W[(size_t)k * HID + n] : 0.f;
    __syncthreads();
    int ko = k0 + tx, no = n0 + ty;
    if (ko < INF) g_wt[(size_t)no * INF + ko] = t[tx][ty];
}

// ---------------- kernel 6: GEMM h = x @ W_conv  (TF32 mma + ldmatrix, 2-stage cp.async) ----
// BM=64, BN=128(full), BK=64. 256 threads = 8 warps (2 along M x 4 along N).
// occ 2 CTAs/SM (104KB smem) -> 157 CTAs in one wave, 16 warps/SM.
#define BM 64
#define BK 64
#define AS_STRIDE 68
#define A_BYTES (BM * AS_STRIDE * 4)          // 17408
#define B_BYTES (HID * AS_STRIDE * 4)         // 34816
#define STAGE_BYTES (A_BYTES + B_BYTES)       // 52224
#define GEMM_SMEM (2 * STAGE_BYTES)           // 104448

__device__ __forceinline__ void g_load(unsigned sb, int stage, int kt,
                                       const float* __restrict__ X, int blockRow, int tid) {
    unsigned abase = sb + stage * STAGE_BYTES;
    unsigned bbase = abase + A_BYTES;
    // A: 64 rows x 64 floats = 1024 float4 -> 4 per thread
#pragma unroll
    for (int q = 0; q < 4; ++q) {
        int chunk = tid * 4 + q;
        int row = chunk >> 4;
        int c16 = chunk & 15;
        int col = kt + c16 * 4;
        int ga = blockRow + row;
        int ok = (ga < NN && col < INF) ? 16 : 0;
        const float* src = ok ? (X + (size_t)ga * INF + col) : X;
        cp_async16(abase + (unsigned)(row * AS_STRIDE + c16 * 4) * 4, src, ok);
    }
    // B: 128 rows (n) x 64 floats (k) = 2048 float4 -> 8 per thread
#pragma unroll
    for (int q = 0; q < 8; ++q) {
        int chunk = tid * 8 + q;
        int row = chunk >> 4;
        int c16 = chunk & 15;
        int col = kt + c16 * 4;
        int ok = (col < INF) ? 16 : 0;
        const float* src = ok ? (g_wt + (size_t)row * INF + col) : g_wt;
        cp_async16(bbase + (unsigned)(row * AS_STRIDE + c16 * 4) * 4, src, ok);
    }
}

__global__ void __launch_bounds__(256, 2) k_gemm(const float* __restrict__ X) {
    extern __shared__ char smem[];
    unsigned sb = smem_u32(smem);

    int tid = threadIdx.x;
    int lane = tid & 31;
    int wid = tid >> 5;
    int wm = wid & 1;        // 2 warps along M (32 rows each)
    int wn = wid >> 1;       // 4 warps along N (32 cols each)
    int g = lane >> 2;
    int tg = lane & 3;

    int blockRow = blockIdx.x * BM;
    const int NT = (INF + BK - 1) / BK;   // 157

    // ldmatrix lane-offset precompute (byte offsets within a stage)
    // A fragment (16x8 tf32): m0=rows 0-7 k0-3, m1=rows 8-15 k0-3, m2=rows 0-7 k4-7, m3=rows 8-15 k4-7
    //   lane l -> row base + (l&15), col (l>>4)*4
    unsigned aoff[2];
#pragma unroll
    for (int mt = 0; mt < 2; ++mt)
        aoff[mt] = (unsigned)(((wm * 32 + mt * 16 + (lane & 15)) * AS_STRIDE + ((lane >> 4) << 2)) * 4);
    // B fragment from n-major BT: m0=n0-7 k0-3 (b0 even), m1=n0-7 k4-7 (b1 even),
    //                             m2=n8-15 k0-3 (b0 odd), m3=n8-15 k4-7 (b1 odd)
    //   lane l -> row base + ((l>>4)<<3) + (l&7), col ((l>>3)&1)*4
    unsigned boff[2];
#pragma unroll
    for (int p = 0; p < 2; ++p)
        boff[p] = (unsigned)(((wn * 32 + p * 16 + ((lane >> 4) << 3) + (lane & 7)) * AS_STRIDE
                              + (((lane >> 3) & 1) << 2)) * 4) + A_BYTES;

    float acc[2][4][4];
#pragma unroll
    for (int mt = 0; mt < 2; ++mt)
#pragma unroll
        for (int nt = 0; nt < 4; ++nt)
#pragma unroll
            for (int q = 0; q < 4; ++q) acc[mt][nt][q] = 0.f;

    // prologue
    g_load(sb, 0, 0, X, blockRow, tid);
    asm volatile("cp.async.commit_group;\n" ::: "memory");

    for (int t = 0; t < NT; ++t) {
        int buf = t & 1;
        if (t + 1 < NT) {
            g_load(sb, (t + 1) & 1, (t + 1) * BK, X, blockRow, tid);
            asm volatile("cp.async.commit_group;\n" ::: "memory");
            asm volatile("cp.async.wait_group 1;\n" ::: "memory");
        } else {
            asm volatile("cp.async.wait_group 0;\n" ::: "memory");
        }
        __syncthreads();

        unsigned sbase = sb + buf * STAGE_BYTES;
#pragma unroll
        for (int ks = 0; ks < 8; ++ks) {
            unsigned kadd = ks * 32;          // 8 floats = 32B per k-step
            unsigned A0[4], A1[4], B0[4], B1[4];
            ldsm4(A0, sbase + aoff[0] + kadd);
            ldsm4(A1, sbase + aoff[1] + kadd);
            ldsm4(B0, sbase + boff[0] + kadd);
            ldsm4(B1, sbase + boff[1] + kadd);
            mma_tf32(acc[0][0], A0, B0[0], B0[1]);
            mma_tf32(acc[0][1], A0, B0[2], B0[3]);
            mma_tf32(acc[0][2], A0, B1[0], B1[1]);
            mma_tf32(acc[0][3], A0, B1[2], B1[3]);
            mma_tf32(acc[1][0], A1, B0[0], B0[1]);
            mma_tf32(acc[1][1], A1, B0[2], B0[3]);
            mma_tf32(acc[1][2], A1, B1[0], B1[1]);
            mma_tf32(acc[1][3], A1, B1[2], B1[3]);
        }
        __syncthreads();
    }

    // epilogue: write h
#pragma unroll
    for (int mt = 0; mt < 2; ++mt) {
#pragma unroll
        for (int nt = 0; nt < 4; ++nt) {
            int r0 = blockRow + wm * 32 + mt * 16 + g;
            int col = wn * 32 + nt * 8 + tg * 2;
            if (r0 < NN)
                *(float2*)&g_h[(size_t)r0 * HID + col] = make_float2(acc[mt][nt][0], acc[mt][nt][1]);
            int r1 = r0 + 8;
            if (r1 < NN)
                *(float2*)&g_h[(size_t)r1 * HID + col] = make_float2(acc[mt][nt][2], acc[mt][nt][3]);
        }
    }
}

// ---------------- kernel 7: fused aggregation + bias + ReLU + linear + softmax ----------------
__global__ void k_agg_final(const float* __restrict__ b_conv,
                            const float* __restrict__ W_lin,
                            const float* __restrict__ b_lin,
                            float* __restrict__ out) {
    int i = blockIdx.x;
    int j = threadIdx.x;
    int lane = j & 31, w = j >> 5;

    int s = g_base[i];
    int e2 = g_base[i + 1];
    float di = g_dinv[i];
    float acc = g_h[(size_t)i * HID + j] * di * di;

    for (int p = s; p < e2; ++p) {
        int r = g_sr[p];
        float wv = g_sw[p];
        acc = fmaf(wv, g_h[(size_t)r * HID + j], acc);
    }

    float v = fmaxf(acc + b_conv[j], 0.f);
    float l0 = v * W_lin[j * 2 + 0];
    float l1 = v * W_lin[j * 2 + 1];
#pragma unroll
    for (int o = 16; o > 0; o >>= 1) {
        l0 += __shfl_xor_sync(0xFFFFFFFFu, l0, o);
        l1 += __shfl_xor_sync(0xFFFFFFFFu, l1, o);
    }
    __shared__ float s0[4], s1[4];
    if (lane == 0) { s0[w] = l0; s1[w] = l1; }
    __syncthreads();
    if (j == 0) {
        float L0 = s0[0] + s0[1] + s0[2] + s0[3] + b_lin[0];
        float L1 = s1[0] + s1[1] + s1[2] + s1[3] + b_lin[1];
        float m = fmaxf(L0, L1);
        float e0 = expf(L0 - m), e1 = expf(L1 - m);
        float inv = 1.f / (e0 + e1);
        out[i * 2 + 0] = e0 * inv;
        out[i * 2 + 1] = e1 * inv;
    }
}

// ---------------- launcher ----------------
extern "C" void kernel_launch(void* const* d_in, const int* in_sizes, int n_in,
                              void* d_out, int out_size) {
    const float* x  = (const float*)d_in[0];
    const void*  ei = d_in[1];
    const float* ew = (const float*)d_in[2];
    const float* Wc = (const float*)d_in[3];
    const float* bc = (const float*)d_in[4];
    const float* Wl = (const float*)d_in[5];
    const float* bl = (const float*)d_in[6];
    float*       out = (float*)d_out;
    int E = in_sizes[2];

    int preBlocks = (E + 255) / 256;
    k_pre0<<<preBlocks, 256>>>((const int*)ei, E);                        // 1
    k_count<<<(E + 255) / 256, 256>>>(ei, ew, E);                         // 2
    k_scan<<<1, 1024>>>();                                                // 3
    k_fill<<<(E + 255) / 256, 256>>>(ei, ew, E);                          // 4
    k_transpose<<<dim3((INF + 31) / 32, HID / 32), dim3(32, 32)>>>(Wc);   // 5

    cudaFuncSetAttribute(k_gemm, cudaFuncAttributeMaxDynamicSharedMemorySize, GEMM_SMEM);
    k_gemm<<<(NN + BM - 1) / BM, 256, GEMM_SMEM>>>(x);                    // 6  <-- ncu -s 5 profiles this

    k_agg_final<<<NN, 128>>>(bc, Wl, bl, out);                            // 7

    (void)n_in; (void)out_size;
}

// round 10
// speedup vs baseline: 1.4195x; 1.4195x over previous
#include <cuda_runtime.h>
#include <cuda_bf16.h>
#include <cstdint>

// Problem constants
#define NN   10000
#define INF  10000
#define HID  128
#define EMAX 320000

// ---------------- scratch (device globals; no allocation allowed) ----------------
__device__ float g_h[(size_t)NN * HID];                  // h = x @ W_conv
__device__ __align__(16) float g_wt[(size_t)HID * INF];  // W^T [128][10000] (n-major) -- unused by GEMM this round, kept for R11
__device__ float g_deg[NN];
__device__ float g_dinv[NN];
__device__ int   g_cnt[NN];
__device__ int   g_base[NN + 1];
__device__ int   g_cursor[NN];
__device__ int   g_sr[EMAX];
__device__ float g_sw[EMAX];
__device__ int   g_is32 = 0;   // sticky dtype flag: 1 => edge_index is int32

// ---------------- helpers ----------------
__device__ __forceinline__ void cp_async16(void* smem_dst, const void* gmem_src, int valid_bytes) {
    unsigned saddr = (unsigned)__cvta_generic_to_shared(smem_dst);
    asm volatile("cp.async.cg.shared.global [%0], [%1], 16, %2;\n"
                 :: "r"(saddr), "l"(gmem_src), "r"(valid_bytes));
}

__device__ __forceinline__ int load_edge_idx(const void* ei, int is32, long long pos) {
    if (is32) return ((const int*)ei)[pos];
    return (int)((const long long*)ei)[pos];
}

__device__ __forceinline__ void mma_tf32(float c[4], const unsigned a[4], const unsigned b[2]) {
    asm volatile(
        "mma.sync.aligned.m16n8k8.row.col.f32.tf32.tf32.f32 "
        "{%0,%1,%2,%3}, {%4,%5,%6,%7}, {%8,%9}, {%0,%1,%2,%3};\n"
        : "+f"(c[0]), "+f"(c[1]), "+f"(c[2]), "+f"(c[3])
        : "r"(a[0]), "r"(a[1]), "r"(a[2]), "r"(a[3]), "r"(b[0]), "r"(b[1]));
}

// ---------------- kernel A: W transpose  W[K][128] -> WT[128][K]  (launch #1) ----------------
__global__ void k_transpose(const float* __restrict__ W) {
    __shared__ float t[32][33];
    int k0 = blockIdx.x * 32, n0 = blockIdx.y * 32;
    int tx = threadIdx.x, ty = threadIdx.y;
    int k = k0 + ty, n = n0 + tx;
    t[ty][tx] = (k < INF) ? W[(size_t)k * HID + n] : 0.f;
    __syncthreads();
    int ko = k0 + tx, no = n0 + ty;
    if (ko < INF) g_wt[(size_t)no * INF + ko] = t[tx][ty];
}

// ---------------- kernel B: init + dtype detect (launch #2) ----------------
__global__ void k_pre0(const int* __restrict__ ei_words, int E) {
    int i = blockIdx.x * blockDim.x + threadIdx.x;
    if (i < NN) {
        g_deg[i] = 1.0f;     // self-loop weight
        g_cnt[i] = 0;
        g_cursor[i] = 0;
    }
    long long idx = 2LL * i + 1;           // odd 32-bit words: zero iff int64
    if (idx < 2LL * E) {
        if (ei_words[idx] != 0) g_is32 = 1;
    }
}

// ---------------- kernel C: degree + count (launch #3) ----------------
__global__ void k_count(const void* __restrict__ ei, const float* __restrict__ ew, int E) {
    int e = blockIdx.x * blockDim.x + threadIdx.x;
    if (e >= E) return;
    int is32 = g_is32;
    int c = load_edge_idx(ei, is32, (long long)E + e);
    atomicAdd(&g_deg[c], ew[e]);
    atomicAdd(&g_cnt[c], 1);
}

// ---------------- kernel D: GEMM h = x @ W_conv  (launch #4 -> gets ncu profile) ----------
// R4-proven structure: BM=64, BN=128(full), BK=32, 256 threads = 8 warps (2M x 4N),
// 2-stage cp.async. Single change vs R4: no cvt.rna.tf32 -- raw fp32 bits into HMMA
// (validated in R9: rel_err 7.6e-5).
#define BM 64
#define BK 32
#define XS_STRIDE 36
#define WS_STRIDE 132
#define XS_ELEMS (BM * XS_STRIDE)        // 2304
#define WS_ELEMS (BK * WS_STRIDE)        // 4224
#define GEMM_SMEM_BYTES ((2 * XS_ELEMS + 2 * WS_ELEMS) * 4)   // 52224

__device__ __forceinline__ void gemm_load(float* xs, float* ws,
                                          const float* __restrict__ X,
                                          const float* __restrict__ W,
                                          int blockRow, int kt, int tid) {
    // X tile: 64 rows x 32 cols. 256 threads * 2 x float4 each.
    int rx = tid >> 3;
    int cx = (tid & 7) * 4;
#pragma unroll
    for (int h = 0; h < 2; ++h) {
        int row = rx + h * 32;
        int grow = blockRow + row;
        int gk = kt + cx;
        int ok = (grow < NN && gk < INF) ? 16 : 0;
        const float* src = ok ? (X + (size_t)grow * INF + gk) : X;
        cp_async16(xs + row * XS_STRIDE + cx, src, ok);
    }
    // W tile: 32 rows (k) x 128 cols (n). 256 threads * 4 x float4 each.
    int kw = tid >> 5;
    int nw = (tid & 31) * 4;
#pragma unroll
    for (int h = 0; h < 4; ++h) {
        int kr = kw + h * 8;
        int gk = kt + kr;
        int ok = (gk < INF) ? 16 : 0;
        const float* src = ok ? (W + (size_t)gk * HID + nw) : W;
        cp_async16(ws + kr * WS_STRIDE + nw, src, ok);
    }
}

__global__ void k_gemm(const float* __restrict__ X, const float* __restrict__ W) {
    extern __shared__ float smem[];
    float* xs0 = smem;
    float* ws0 = smem + 2 * XS_ELEMS;

    int tid = threadIdx.x;
    int lane = tid & 31;
    int wid = tid >> 5;
    int wm = wid & 1;        // 2 warps along M (32 rows each)
    int wn = wid >> 1;       // 4 warps along N (32 cols each)
    int g = lane >> 2;       // groupID
    int tg = lane & 3;       // thread-in-group

    int blockRow = blockIdx.x * BM;
    const int NT = (INF + BK - 1) / BK;   // 313

    float acc[2][4][4];
#pragma unroll
    for (int mt = 0; mt < 2; ++mt)
#pragma unroll
        for (int nt = 0; nt < 4; ++nt)
#pragma unroll
            for (int q = 0; q < 4; ++q) acc[mt][nt][q] = 0.f;

    // prologue
    gemm_load(xs0, ws0, X, W, blockRow, 0, tid);
    asm volatile("cp.async.commit_group;\n" ::: "memory");

    for (int t = 0; t < NT; ++t) {
        int buf = t & 1;
        if (t + 1 < NT) {
            int nbuf = (t + 1) & 1;
            gemm_load(xs0 + nbuf * XS_ELEMS, ws0 + nbuf * WS_ELEMS, X, W, blockRow, (t + 1) * BK, tid);
            asm volatile("cp.async.commit_group;\n" ::: "memory");
            asm volatile("cp.async.wait_group 1;\n" ::: "memory");
        } else {
            asm volatile("cp.async.wait_group 0;\n" ::: "memory");
        }
        __syncthreads();

        const float* xs = xs0 + buf * XS_ELEMS;
        const float* ws = ws0 + buf * WS_ELEMS;

#pragma unroll
        for (int ks = 0; ks < 4; ++ks) {
            int k0 = ks * 8;
            unsigned A[2][4];
#pragma unroll
            for (int mt = 0; mt < 2; ++mt) {
                int r0 = wm * 32 + mt * 16 + g;
                A[mt][0] = __float_as_uint(xs[r0 * XS_STRIDE + k0 + tg]);
                A[mt][1] = __float_as_uint(xs[(r0 + 8) * XS_STRIDE + k0 + tg]);
                A[mt][2] = __float_as_uint(xs[r0 * XS_STRIDE + k0 + tg + 4]);
                A[mt][3] = __float_as_uint(xs[(r0 + 8) * XS_STRIDE + k0 + tg + 4]);
            }
            unsigned B[4][2];
#pragma unroll
            for (int nt = 0; nt < 4; ++nt) {
                int nc = wn * 32 + nt * 8 + g;
                B[nt][0] = __float_as_uint(ws[(k0 + tg) * WS_STRIDE + nc]);
                B[nt][1] = __float_as_uint(ws[(k0 + tg + 4) * WS_STRIDE + nc]);
            }
#pragma unroll
            for (int mt = 0; mt < 2; ++mt)
#pragma unroll
                for (int nt = 0; nt < 4; ++nt)
                    mma_tf32(acc[mt][nt], A[mt], B[nt]);
        }
        __syncthreads();
    }

    // epilogue: write h
#pragma unroll
    for (int mt = 0; mt < 2; ++mt) {
#pragma unroll
        for (int nt = 0; nt < 4; ++nt) {
            int r0 = blockRow + wm * 32 + mt * 16 + g;
            int col = wn * 32 + nt * 8 + tg * 2;
            if (r0 < NN)
                *(float2*)&g_h[(size_t)r0 * HID + col] = make_float2(acc[mt][nt][0], acc[mt][nt][1]);
            int r1 = r0 + 8;
            if (r1 < NN)
                *(float2*)&g_h[(size_t)r1 * HID + col] = make_float2(acc[mt][nt][2], acc[mt][nt][3]);
        }
    }
}

// ---------------- kernel E: dinv + exclusive scan (launch #5) ----------------
__global__ void k_scan() {
    const int PER = 10;
    int t = threadIdx.x;
    int lane = t & 31, w = t >> 5;
#pragma unroll
    for (int p = 0; p < PER; ++p) {
        int idx = t * PER + p;
        if (idx < NN) {
            float d = g_deg[idx];
            g_dinv[idx] = (d > 0.f) ? rsqrtf(d) : 0.f;
        }
    }
    int local[PER];
    int sum = 0;
#pragma unroll
    for (int p = 0; p < PER; ++p) {
        int idx = t * PER + p;
        int v = (idx < NN) ? g_cnt[idx] : 0;
        local[p] = sum;
        sum += v;
    }
    int x = sum;
#pragma unroll
    for (int o = 1; o < 32; o <<= 1) {
        int y = __shfl_up_sync(0xFFFFFFFFu, x, o);
        if (lane >= o) x += y;
    }
    __shared__ int ws[32];
    if (lane == 31) ws[w] = x;
    __syncthreads();
    if (w == 0) {
        int v = ws[lane];
#pragma unroll
        for (int o = 1; o < 32; o <<= 1) {
            int y = __shfl_up_sync(0xFFFFFFFFu, v, o);
            if (lane >= o) v += y;
        }
        ws[lane] = v;
    }
    __syncthreads();
    int base = (x - sum) + (w > 0 ? ws[w - 1] : 0);
#pragma unroll
    for (int p = 0; p < PER; ++p) {
        int idx = t * PER + p;
        if (idx <= NN) g_base[idx] = base + local[p];
    }
}

// ---------------- kernel F: fill CSR buckets (launch #6) ----------------
__global__ void k_fill(const void* __restrict__ ei, const float* __restrict__ ew, int E) {
    int e = blockIdx.x * blockDim.x + threadIdx.x;
    if (e >= E) return;
    int is32 = g_is32;
    int r = load_edge_idx(ei, is32, e);
    int c = load_edge_idx(ei, is32, (long long)E + e);
    float wv = ew[e] * g_dinv[r] * g_dinv[c];
    int pos = atomicAdd(&g_cursor[c], 1);
    g_sr[g_base[c] + pos] = r;
    g_sw[g_base[c] + pos] = wv;
}

// ---------------- kernel G: fused aggregation + bias + ReLU + linear + softmax (launch #7) ----
// CSR slice staged in smem (kills per-edge L2-broadcast latency chain); dual accumulators.
#define DEG_CAP 192
__global__ void k_agg_final(const float* __restrict__ b_conv,
                            const float* __restrict__ W_lin,
                            const float* __restrict__ b_lin,
                            float* __restrict__ out) {
    __shared__ int   ssr[DEG_CAP];
    __shared__ float ssw[DEG_CAP];
    int i = blockIdx.x;
    int j = threadIdx.x;
    int lane = j & 31, w = j >> 5;

    int s = g_base[i];
    int e2 = g_base[i + 1];
    int deg = e2 - s;
    bool fits = (deg <= DEG_CAP);
    if (fits) {
        for (int p = j; p < deg; p += 128) {
            ssr[p] = g_sr[s + p];
            ssw[p] = g_sw[s + p];
        }
    }
    __syncthreads();

    float di = g_dinv[i];
    float acc0 = g_h[(size_t)i * HID + j] * di * di;
    float acc1 = 0.f;

    if (fits) {
        int p = 0;
        for (; p + 1 < deg; p += 2) {
            acc0 = fmaf(ssw[p],     g_h[(size_t)ssr[p]     * HID + j], acc0);
            acc1 = fmaf(ssw[p + 1], g_h[(size_t)ssr[p + 1] * HID + j], acc1);
        }
        if (p < deg)
            acc0 = fmaf(ssw[p], g_h[(size_t)ssr[p] * HID + j], acc0);
    } else {
        for (int p = s; p < e2; ++p)
            acc0 = fmaf(g_sw[p], g_h[(size_t)g_sr[p] * HID + j], acc0);
    }
    float acc = acc0 + acc1;

    float v = fmaxf(acc + b_conv[j], 0.f);
    float l0 = v * W_lin[j * 2 + 0];
    float l1 = v * W_lin[j * 2 + 1];
#pragma unroll
    for (int o = 16; o > 0; o >>= 1) {
        l0 += __shfl_xor_sync(0xFFFFFFFFu, l0, o);
        l1 += __shfl_xor_sync(0xFFFFFFFFu, l1, o);
    }
    __shared__ float s0[4], s1[4];
    if (lane == 0) { s0[w] = l0; s1[w] = l1; }
    __syncthreads();
    if (j == 0) {
        float L0 = s0[0] + s0[1] + s0[2] + s0[3] + b_lin[0];
        float L1 = s1[0] + s1[1] + s1[2] + s1[3] + b_lin[1];
        float m = fmaxf(L0, L1);
        float e0 = expf(L0 - m), e1 = expf(L1 - m);
        float inv = 1.f / (e0 + e1);
        out[i * 2 + 0] = e0 * inv;
        out[i * 2 + 1] = e1 * inv;
    }
}

// ---------------- launcher ----------------
extern "C" void kernel_launch(void* const* d_in, const int* in_sizes, int n_in,
                              void* d_out, int out_size) {
    const float* x  = (const float*)d_in[0];
    const void*  ei = d_in[1];
    const float* ew = (const float*)d_in[2];
    const float* Wc = (const float*)d_in[3];
    const float* bc = (const float*)d_in[4];
    const float* Wl = (const float*)d_in[5];
    const float* bl = (const float*)d_in[6];
    float*       out = (float*)d_out;
    int E = in_sizes[2];

    int preBlocks = (E + 255) / 256;

    k_transpose<<<dim3((INF + 31) / 32, HID / 32), dim3(32, 32)>>>(Wc);   // 1
    k_pre0<<<preBlocks, 256>>>((const int*)ei, E);                        // 2
    k_count<<<(E + 255) / 256, 256>>>(ei, ew, E);                         // 3

    cudaFuncSetAttribute(k_gemm, cudaFuncAttributeMaxDynamicSharedMemorySize, GEMM_SMEM_BYTES);
    k_gemm<<<(NN + BM - 1) / BM, 256, GEMM_SMEM_BYTES>>>(x, Wc);          // 4  <-- ncu profiles launch #4

    k_scan<<<1, 1024>>>();                                                // 5
    k_fill<<<(E + 255) / 256, 256>>>(ei, ew, E);                          // 6
    k_agg_final<<<NN, 128>>>(bc, Wl, bl, out);                            // 7

    (void)n_in; (void)out_size;
}

// round 11
// speedup vs baseline: 1.5648x; 1.1024x over previous
#include <cuda_runtime.h>
#include <cuda_bf16.h>
#include <cstdint>

// Problem constants
#define NN   10000
#define INF  10000
#define HID  128
#define EMAX 320000
#define SPLITS 8
#define NH (NN * HID)

// ---------------- scratch (device globals; no allocation allowed) ----------------
__device__ float g_h[(size_t)NH];                        // h = x @ W_conv (reduced)
__device__ __align__(16) float g_hp[(size_t)SPLITS * NH];// split-K partials (41 MB)
__device__ __align__(16) float g_wt[(size_t)HID * INF];  // W^T (kept for future rounds)
__device__ float g_deg[NN];
__device__ float g_dinv[NN];
__device__ int   g_cnt[NN];
__device__ int   g_base[NN + 1];
__device__ int   g_cursor[NN];
__device__ int   g_sr[EMAX];
__device__ float g_sw[EMAX];
__device__ int   g_is32 = 0;   // sticky dtype flag: 1 => edge_index is int32

// ---------------- helpers ----------------
__device__ __forceinline__ void cp_async16(void* smem_dst, const void* gmem_src, int valid_bytes) {
    unsigned saddr = (unsigned)__cvta_generic_to_shared(smem_dst);
    asm volatile("cp.async.cg.shared.global [%0], [%1], 16, %2;\n"
                 :: "r"(saddr), "l"(gmem_src), "r"(valid_bytes));
}

__device__ __forceinline__ int load_edge_idx(const void* ei, int is32, long long pos) {
    if (is32) return ((const int*)ei)[pos];
    return (int)((const long long*)ei)[pos];
}

__device__ __forceinline__ void mma_tf32(float c[4], const unsigned a[4], const unsigned b[2]) {
    asm volatile(
        "mma.sync.aligned.m16n8k8.row.col.f32.tf32.tf32.f32 "
        "{%0,%1,%2,%3}, {%4,%5,%6,%7}, {%8,%9}, {%0,%1,%2,%3};\n"
        : "+f"(c[0]), "+f"(c[1]), "+f"(c[2]), "+f"(c[3])
        : "r"(a[0]), "r"(a[1]), "r"(a[2]), "r"(a[3]), "r"(b[0]), "r"(b[1]));
}

// ---------------- kernel A: W transpose (launch #1; g_wt kept for future use) ----------------
__global__ void k_transpose(const float* __restrict__ W) {
    __shared__ float t[32][33];
    int k0 = blockIdx.x * 32, n0 = blockIdx.y * 32;
    int tx = threadIdx.x, ty = threadIdx.y;
    int k = k0 + ty, n = n0 + tx;
    t[ty][tx] = (k < INF) ? W[(size_t)k * HID + n] : 0.f;
    __syncthreads();
    int ko = k0 + tx, no = n0 + ty;
    if (ko < INF) g_wt[(size_t)no * INF + ko] = t[tx][ty];
}

// ---------------- kernel B: init + dtype detect (launch #2) ----------------
__global__ void k_pre0(const int* __restrict__ ei_words, int E) {
    int i = blockIdx.x * blockDim.x + threadIdx.x;
    if (i < NN) {
        g_deg[i] = 1.0f;     // self-loop weight
        g_cnt[i] = 0;
        g_cursor[i] = 0;
    }
    long long idx = 2LL * i + 1;           // odd 32-bit words: zero iff int64
    if (idx < 2LL * E) {
        if (ei_words[idx] != 0) g_is32 = 1;
    }
}

// ---------------- kernel C: degree + count (launch #3) ----------------
__global__ void k_count(const void* __restrict__ ei, const float* __restrict__ ew, int E) {
    int e = blockIdx.x * blockDim.x + threadIdx.x;
    if (e >= E) return;
    int is32 = g_is32;
    int c = load_edge_idx(ei, is32, (long long)E + e);
    atomicAdd(&g_deg[c], ew[e]);
    atomicAdd(&g_cnt[c], 1);
}

// ---------------- kernel D: split-K GEMM (launch #4 -> ncu profile) ----------
// Proven R10 structure (BM=64, BN=128, BK=32, 8 warps, 2-stage cp.async, raw-bits tf32 mma).
// NEW: blockIdx.y = K-split (8 partitions of <=40 chunks) -> grid 1256, occ 4 CTAs/SM,
// 32 warps/SM for latency hiding. Partials to g_hp, reduced by k_reduce.
#define BM 64
#define BK 32
#define NCHUNK 313                       // ceil(INF/BK)
#define CPS 40                           // chunks per split (8*40 >= 313)
#define XS_STRIDE 36
#define WS_STRIDE 132
#define XS_ELEMS (BM * XS_STRIDE)        // 2304
#define WS_ELEMS (BK * WS_STRIDE)        // 4224
#define GEMM_SMEM_BYTES ((2 * XS_ELEMS + 2 * WS_ELEMS) * 4)   // 52224

__device__ __forceinline__ void gemm_load(float* xs, float* ws,
                                          const float* __restrict__ X,
                                          const float* __restrict__ W,
                                          int blockRow, int kt, int tid) {
    int rx = tid >> 3;
    int cx = (tid & 7) * 4;
#pragma unroll
    for (int h = 0; h < 2; ++h) {
        int row = rx + h * 32;
        int grow = blockRow + row;
        int gk = kt + cx;
        int ok = (grow < NN && gk < INF) ? 16 : 0;
        const float* src = ok ? (X + (size_t)grow * INF + gk) : X;
        cp_async16(xs + row * XS_STRIDE + cx, src, ok);
    }
    int kw = tid >> 5;
    int nw = (tid & 31) * 4;
#pragma unroll
    for (int h = 0; h < 4; ++h) {
        int kr = kw + h * 8;
        int gk = kt + kr;
        int ok = (gk < INF) ? 16 : 0;
        const float* src = ok ? (W + (size_t)gk * HID + nw) : W;
        cp_async16(ws + kr * WS_STRIDE + nw, src, ok);
    }
}

__global__ void __launch_bounds__(256) k_gemm(const float* __restrict__ X, const float* __restrict__ W) {
    extern __shared__ float smem[];
    float* xs0 = smem;
    float* ws0 = smem + 2 * XS_ELEMS;

    int tid = threadIdx.x;
    int lane = tid & 31;
    int wid = tid >> 5;
    int wm = wid & 1;
    int wn = wid >> 1;
    int g = lane >> 2;
    int tg = lane & 3;

    int blockRow = blockIdx.x * BM;
    int sp = blockIdx.y;
    int c0 = sp * CPS;
    int c1 = min(c0 + CPS, NCHUNK);

    float acc[2][4][4];
#pragma unroll
    for (int mt = 0; mt < 2; ++mt)
#pragma unroll
        for (int nt = 0; nt < 4; ++nt)
#pragma unroll
            for (int q = 0; q < 4; ++q) acc[mt][nt][q] = 0.f;

    // prologue
    gemm_load(xs0, ws0, X, W, blockRow, c0 * BK, tid);
    asm volatile("cp.async.commit_group;\n" ::: "memory");

    for (int t = c0; t < c1; ++t) {
        int buf = (t - c0) & 1;
        if (t + 1 < c1) {
            int nbuf = (t + 1 - c0) & 1;
            gemm_load(xs0 + nbuf * XS_ELEMS, ws0 + nbuf * WS_ELEMS, X, W, blockRow, (t + 1) * BK, tid);
            asm volatile("cp.async.commit_group;\n" ::: "memory");
            asm volatile("cp.async.wait_group 1;\n" ::: "memory");
        } else {
            asm volatile("cp.async.wait_group 0;\n" ::: "memory");
        }
        __syncthreads();

        const float* xs = xs0 + buf * XS_ELEMS;
        const float* ws = ws0 + buf * WS_ELEMS;

#pragma unroll
        for (int ks = 0; ks < 4; ++ks) {
            int k0 = ks * 8;
            unsigned A[2][4];
#pragma unroll
            for (int mt = 0; mt < 2; ++mt) {
                int r0 = wm * 32 + mt * 16 + g;
                A[mt][0] = __float_as_uint(xs[r0 * XS_STRIDE + k0 + tg]);
                A[mt][1] = __float_as_uint(xs[(r0 + 8) * XS_STRIDE + k0 + tg]);
                A[mt][2] = __float_as_uint(xs[r0 * XS_STRIDE + k0 + tg + 4]);
                A[mt][3] = __float_as_uint(xs[(r0 + 8) * XS_STRIDE + k0 + tg + 4]);
            }
            unsigned B[4][2];
#pragma unroll
            for (int nt = 0; nt < 4; ++nt) {
                int nc = wn * 32 + nt * 8 + g;
                B[nt][0] = __float_as_uint(ws[(k0 + tg) * WS_STRIDE + nc]);
                B[nt][1] = __float_as_uint(ws[(k0 + tg + 4) * WS_STRIDE + nc]);
            }
#pragma unroll
            for (int mt = 0; mt < 2; ++mt)
#pragma unroll
                for (int nt = 0; nt < 4; ++nt)
                    mma_tf32(acc[mt][nt], A[mt], B[nt]);
        }
        __syncthreads();
    }

    // epilogue: write partial h for this split
    float* hp = g_hp + (size_t)sp * NH;
#pragma unroll
    for (int mt = 0; mt < 2; ++mt) {
#pragma unroll
        for (int nt = 0; nt < 4; ++nt) {
            int r0 = blockRow + wm * 32 + mt * 16 + g;
            int col = wn * 32 + nt * 8 + tg * 2;
            if (r0 < NN)
                *(float2*)&hp[(size_t)r0 * HID + col] = make_float2(acc[mt][nt][0], acc[mt][nt][1]);
            int r1 = r0 + 8;
            if (r1 < NN)
                *(float2*)&hp[(size_t)r1 * HID + col] = make_float2(acc[mt][nt][2], acc[mt][nt][3]);
        }
    }
}

// ---------------- kernel D2: reduce split-K partials (launch #5) ----------------
__global__ void k_reduce() {
    int i = blockIdx.x * blockDim.x + threadIdx.x;   // float4 index
    const int TOT = NH / 4;                          // 320000
    if (i >= TOT) return;
    const float4* p = (const float4*)g_hp;
    float4 s = p[i];
#pragma unroll
    for (int q = 1; q < SPLITS; ++q) {
        float4 v = p[(size_t)q * TOT + i];
        s.x += v.x; s.y += v.y; s.z += v.z; s.w += v.w;
    }
    ((float4*)g_h)[i] = s;
}

// ---------------- kernel E: dinv + exclusive scan (launch #6) ----------------
__global__ void k_scan() {
    const int PER = 10;
    int t = threadIdx.x;
    int lane = t & 31, w = t >> 5;
#pragma unroll
    for (int p = 0; p < PER; ++p) {
        int idx = t * PER + p;
        if (idx < NN) {
            float d = g_deg[idx];
            g_dinv[idx] = (d > 0.f) ? rsqrtf(d) : 0.f;
        }
    }
    int local[PER];
    int sum = 0;
#pragma unroll
    for (int p = 0; p < PER; ++p) {
        int idx = t * PER + p;
        int v = (idx < NN) ? g_cnt[idx] : 0;
        local[p] = sum;
        sum += v;
    }
    int x = sum;
#pragma unroll
    for (int o = 1; o < 32; o <<= 1) {
        int y = __shfl_up_sync(0xFFFFFFFFu, x, o);
        if (lane >= o) x += y;
    }
    __shared__ int ws[32];
    if (lane == 31) ws[w] = x;
    __syncthreads();
    if (w == 0) {
        int v = ws[lane];
#pragma unroll
        for (int o = 1; o < 32; o <<= 1) {
            int y = __shfl_up_sync(0xFFFFFFFFu, v, o);
            if (lane >= o) v += y;
        }
        ws[lane] = v;
    }
    __syncthreads();
    int base = (x - sum) + (w > 0 ? ws[w - 1] : 0);
#pragma unroll
    for (int p = 0; p < PER; ++p) {
        int idx = t * PER + p;
        if (idx <= NN) g_base[idx] = base + local[p];
    }
}

// ---------------- kernel F: fill CSR buckets (launch #7) ----------------
__global__ void k_fill(const void* __restrict__ ei, const float* __restrict__ ew, int E) {
    int e = blockIdx.x * blockDim.x + threadIdx.x;
    if (e >= E) return;
    int is32 = g_is32;
    int r = load_edge_idx(ei, is32, e);
    int c = load_edge_idx(ei, is32, (long long)E + e);
    float wv = ew[e] * g_dinv[r] * g_dinv[c];
    int pos = atomicAdd(&g_cursor[c], 1);
    g_sr[g_base[c] + pos] = r;
    g_sw[g_base[c] + pos] = wv;
}

// ---------------- kernel G: fused aggregation + bias + ReLU + linear + softmax (launch #8) ----
#define DEG_CAP 192
__global__ void k_agg_final(const float* __restrict__ b_conv,
                            const float* __restrict__ W_lin,
                            const float* __restrict__ b_lin,
                            float* __restrict__ out) {
    __shared__ int   ssr[DEG_CAP];
    __shared__ float ssw[DEG_CAP];
    int i = blockIdx.x;
    int j = threadIdx.x;
    int lane = j & 31, w = j >> 5;

    int s = g_base[i];
    int e2 = g_base[i + 1];
    int deg = e2 - s;
    bool fits = (deg <= DEG_CAP);
    if (fits) {
        for (int p = j; p < deg; p += 128) {
            ssr[p] = g_sr[s + p];
            ssw[p] = g_sw[s + p];
        }
    }
    __syncthreads();

    float di = g_dinv[i];
    float acc0 = g_h[(size_t)i * HID + j] * di * di;
    float acc1 = 0.f;

    if (fits) {
        int p = 0;
        for (; p + 1 < deg; p += 2) {
            acc0 = fmaf(ssw[p],     g_h[(size_t)ssr[p]     * HID + j], acc0);
            acc1 = fmaf(ssw[p + 1], g_h[(size_t)ssr[p + 1] * HID + j], acc1);
        }
        if (p < deg)
            acc0 = fmaf(ssw[p], g_h[(size_t)ssr[p] * HID + j], acc0);
    } else {
        for (int p = s; p < e2; ++p)
            acc0 = fmaf(g_sw[p], g_h[(size_t)g_sr[p] * HID + j], acc0);
    }
    float acc = acc0 + acc1;

    float v = fmaxf(acc + b_conv[j], 0.f);
    float l0 = v * W_lin[j * 2 + 0];
    float l1 = v * W_lin[j * 2 + 1];
#pragma unroll
    for (int o = 16; o > 0; o >>= 1) {
        l0 += __shfl_xor_sync(0xFFFFFFFFu, l0, o);
        l1 += __shfl_xor_sync(0xFFFFFFFFu, l1, o);
    }
    __shared__ float s0[4], s1[4];
    if (lane == 0) { s0[w] = l0; s1[w] = l1; }
    __syncthreads();
    if (j == 0) {
        float L0 = s0[0] + s0[1] + s0[2] + s0[3] + b_lin[0];
        float L1 = s1[0] + s1[1] + s1[2] + s1[3] + b_lin[1];
        float m = fmaxf(L0, L1);
        float e0 = expf(L0 - m), e1 = expf(L1 - m);
        float inv = 1.f / (e0 + e1);
        out[i * 2 + 0] = e0 * inv;
        out[i * 2 + 1] = e1 * inv;
    }
}

// ---------------- launcher ----------------
extern "C" void kernel_launch(void* const* d_in, const int* in_sizes, int n_in,
                              void* d_out, int out_size) {
    const float* x  = (const float*)d_in[0];
    const void*  ei = d_in[1];
    const float* ew = (const float*)d_in[2];
    const float* Wc = (const float*)d_in[3];
    const float* bc = (const float*)d_in[4];
    const float* Wl = (const float*)d_in[5];
    const float* bl = (const float*)d_in[6];
    float*       out = (float*)d_out;
    int E = in_sizes[2];

    int preBlocks = (E + 255) / 256;

    k_transpose<<<dim3((INF + 31) / 32, HID / 32), dim3(32, 32)>>>(Wc);   // 1
    k_pre0<<<preBlocks, 256>>>((const int*)ei, E);                        // 2
    k_count<<<(E + 255) / 256, 256>>>(ei, ew, E);                         // 3

    cudaFuncSetAttribute(k_gemm, cudaFuncAttributeMaxDynamicSharedMemorySize, GEMM_SMEM_BYTES);
    k_gemm<<<dim3((NN + BM - 1) / BM, SPLITS), 256, GEMM_SMEM_BYTES>>>(x, Wc);  // 4  <-- ncu profiles #4

    k_reduce<<<(NH / 4 + 255) / 256, 256>>>();                            // 5
    k_scan<<<1, 1024>>>();                                                // 6
    k_fill<<<(E + 255) / 256, 256>>>(ei, ew, E);                          // 7
    k_agg_final<<<NN, 128>>>(bc, Wl, bl, out);                            // 8

    (void)n_in; (void)out_size;
}

// round 14
// speedup vs baseline: 1.8843x; 1.2041x over previous
#include <cuda_runtime.h>
#include <cuda_bf16.h>
#include <cstdint>

// Problem constants
#define NN   10000
#define INF  10000
#define HID  128
#define EMAX 320000
#define SPLITS 4
#define NH (NN * HID)

// ---------------- scratch (device globals; no allocation allowed) ----------------
__device__ float g_h[(size_t)NH];                        // h = x @ W_conv (reduced)
__device__ __align__(16) float g_hp[(size_t)SPLITS * NH];// split-K partials (20.5 MB)
__device__ __align__(16) float g_wt[(size_t)HID * INF];  // W^T [128][10000] (n-major)
__device__ float g_deg[NN];
__device__ float g_dinv[NN];
__device__ int   g_cnt[NN];
__device__ int   g_base[NN + 1];
__device__ int   g_cursor[NN];
__device__ int   g_sr[EMAX];
__device__ float g_sw[EMAX];
__device__ int   g_is32 = 0;   // sticky dtype flag: 1 => edge_index is int32

// ---------------- helpers ----------------
__device__ __forceinline__ unsigned smem_u32(const void* p) {
    unsigned a;
    asm("{ .reg .u64 t; cvta.to.shared.u64 t, %1; cvt.u32.u64 %0, t; }" : "=r"(a) : "l"(p));
    return a;
}

__device__ __forceinline__ void cp_async16(void* smem_dst, const void* gmem_src, int valid_bytes) {
    unsigned saddr = (unsigned)__cvta_generic_to_shared(smem_dst);
    asm volatile("cp.async.cg.shared.global [%0], [%1], 16, %2;\n"
                 :: "r"(saddr), "l"(gmem_src), "r"(valid_bytes));
}

__device__ __forceinline__ int load_edge_idx(const void* ei, int is32, long long pos) {
    if (is32) return ((const int*)ei)[pos];
    return (int)((const long long*)ei)[pos];
}

__device__ __forceinline__ void ldsm4(unsigned r[4], unsigned saddr) {
    asm volatile("ldmatrix.sync.aligned.m8n8.x4.shared.b16 {%0,%1,%2,%3}, [%4];"
                 : "=r"(r[0]), "=r"(r[1]), "=r"(r[2]), "=r"(r[3]) : "r"(saddr));
}

__device__ __forceinline__ void mma_tf32(float c[4], const unsigned a[4], const unsigned b0, const unsigned b1) {
    asm volatile(
        "mma.sync.aligned.m16n8k8.row.col.f32.tf32.tf32.f32 "
        "{%0,%1,%2,%3}, {%4,%5,%6,%7}, {%8,%9}, {%0,%1,%2,%3};\n"
        : "+f"(c[0]), "+f"(c[1]), "+f"(c[2]), "+f"(c[3])
        : "r"(a[0]), "r"(a[1]), "r"(a[2]), "r"(a[3]), "r"(b0), "r"(b1));
}

// ---------------- kernel A: W transpose  W[K][128] -> WT[128][K]  (launch #1) ----------------
__global__ void k_transpose(const float* __restrict__ W) {
    __shared__ float t[32][33];
    int k0 = blockIdx.x * 32, n0 = blockIdx.y * 32;
    int tx = threadIdx.x, ty = threadIdx.y;
    int k = k0 + ty, n = n0 + tx;
    t[ty][tx] = (k < INF) ? W[(size_t)k * HID + n] : 0.f;
    __syncthreads();
    int ko = k0 + tx, no = n0 + ty;
    if (ko < INF) g_wt[(size_t)no * INF + ko] = t[tx][ty];
}

// ---------------- kernel B: init + dtype detect (launch #2) ----------------
__global__ void k_pre0(const int* __restrict__ ei_words, int E) {
    int i = blockIdx.x * blockDim.x + threadIdx.x;
    if (i < NN) {
        g_deg[i] = 1.0f;     // self-loop weight
        g_cnt[i] = 0;
        g_cursor[i] = 0;
    }
    long long idx = 2LL * i + 1;           // odd 32-bit words: zero iff int64
    if (idx < 2LL * E) {
        if (ei_words[idx] != 0) g_is32 = 1;
    }
}

// ---------------- kernel C: degree + count (launch #3) ----------------
__global__ void k_count(const void* __restrict__ ei, const float* __restrict__ ew, int E) {
    int e = blockIdx.x * blockDim.x + threadIdx.x;
    if (e >= E) return;
    int is32 = g_is32;
    int c = load_edge_idx(ei, is32, (long long)E + e);
    atomicAdd(&g_deg[c], ew[e]);
    atomicAdd(&g_cnt[c], 1);
}

// ---------------- kernel D: split-K GEMM with ldmatrix feed (launch #4 -> ncu) ----------
// BM=64, BN=128(full), BK=32, 8 warps (2M x 4N). A row-major from X, B n-major from g_wt.
// Fragment feed: 4 x ldmatrix.x4 per k-step (layout verified in R9), conflict-free
// (row stride 144B). Split-K (4 partitions of <=79 chunks) keeps occ 4 (55.3KB smem/CTA).
#define BM 64
#define BK 32
#define NCHUNK 313
#define CPS 79                            // 4*79 >= 313
#define ASTR 36                           // floats; 144B row stride
#define A_BYTES (BM * ASTR * 4)           // 9216
#define B_BYTES (HID * ASTR * 4)          // 18432
#define STAGE_BYTES (A_BYTES + B_BYTES)   // 27648
#define GEMM_SMEM (2 * STAGE_BYTES)       // 55296

__device__ __forceinline__ void gemm_load(char* smem, int stage, int kt,
                                          const float* __restrict__ X,
                                          int blockRow, int tid) {
    char* abase = smem + stage * STAGE_BYTES;
    char* bbase = abase + A_BYTES;
    // A: 64 rows x 32 floats = 512 float4 -> 2 per thread
#pragma unroll
    for (int q = 0; q < 2; ++q) {
        int chunk = tid * 2 + q;
        int row = chunk >> 3;
        int c16 = chunk & 7;
        int col = kt + c16 * 4;
        int grow = blockRow + row;
        int ok = (grow < NN && col < INF) ? 16 : 0;
        const float* src = ok ? (X + (size_t)grow * INF + col) : X;
        cp_async16(abase + (row * ASTR + c16 * 4) * 4, src, ok);
    }
    // B: 128 n-rows x 32 floats = 1024 float4 -> 4 per thread (from g_wt, n-major)
#pragma unroll
    for (int q = 0; q < 4; ++q) {
        int chunk = tid * 4 + q;
        int row = chunk >> 3;
        int c16 = chunk & 7;
        int col = kt + c16 * 4;
        int ok = (col < INF) ? 16 : 0;
        const float* src = ok ? (g_wt + (size_t)row * INF + col) : g_wt;
        cp_async16(bbase + (row * ASTR + c16 * 4) * 4, src, ok);
    }
}

__global__ void __launch_bounds__(256, 4) k_gemm(const float* __restrict__ X) {
    extern __shared__ char smem[];
    unsigned sb = smem_u32(smem);

    int tid = threadIdx.x;
    int lane = tid & 31;
    int wid = tid >> 5;
    int wm = wid & 1;        // 2 warps along M
    int wn = wid >> 1;       // 4 warps along N
    int g = lane >> 2;
    int tg = lane & 3;

    int blockRow = blockIdx.x * BM;
    int sp = blockIdx.y;
    int c0 = sp * CPS;
    int c1 = min(c0 + CPS, NCHUNK);

    // ldmatrix lane offsets (bytes within a stage) — verified mapping from R9
    unsigned aoff[2];
#pragma unroll
    for (int mt = 0; mt < 2; ++mt)
        aoff[mt] = (unsigned)(((wm * 32 + mt * 16 + (lane & 15)) * ASTR + ((lane >> 4) << 2)) * 4);
    unsigned boff[2];
#pragma unroll
    for (int p = 0; p < 2; ++p)
        boff[p] = (unsigned)(((wn * 32 + p * 16 + ((lane >> 4) << 3) + (lane & 7)) * ASTR
                              + (((lane >> 3) & 1) << 2)) * 4) + A_BYTES;

    float acc[2][4][4];
#pragma unroll
    for (int mt = 0; mt < 2; ++mt)
#pragma unroll
        for (int nt = 0; nt < 4; ++nt)
#pragma unroll
            for (int q = 0; q < 4; ++q) acc[mt][nt][q] = 0.f;

    // prologue
    gemm_load(smem, 0, c0 * BK, X, blockRow, tid);
    asm volatile("cp.async.commit_group;\n" ::: "memory");

    for (int t = c0; t < c1; ++t) {
        int buf = (t - c0) & 1;
        if (t + 1 < c1) {
            gemm_load(smem, (t + 1 - c0) & 1, (t + 1) * BK, X, blockRow, tid);
            asm volatile("cp.async.commit_group;\n" ::: "memory");
            asm volatile("cp.async.wait_group 1;\n" ::: "memory");
        } else {
            asm volatile("cp.async.wait_group 0;\n" ::: "memory");
        }
        __syncthreads();

        unsigned sbase = sb + buf * STAGE_BYTES;
#pragma unroll
        for (int ks = 0; ks < 4; ++ks) {
            unsigned kadd = ks * 32;      // 8 floats per k-step
            unsigned A0[4], A1[4], B0[4], B1[4];
            ldsm4(A0, sbase + aoff[0] + kadd);
            ldsm4(A1, sbase + aoff[1] + kadd);
            ldsm4(B0, sbase + boff[0] + kadd);
            ldsm4(B1, sbase + boff[1] + kadd);
            mma_tf32(acc[0][0], A0, B0[0], B0[1]);
            mma_tf32(acc[0][1], A0, B0[2], B0[3]);
            mma_tf32(acc[0][2], A0, B1[0], B1[1]);
            mma_tf32(acc[0][3], A0, B1[2], B1[3]);
            mma_tf32(acc[1][0], A1, B0[0], B0[1]);
            mma_tf32(acc[1][1], A1, B0[2], B0[3]);
            mma_tf32(acc[1][2], A1, B1[0], B1[1]);
            mma_tf32(acc[1][3], A1, B1[2], B1[3]);
        }
        __syncthreads();
    }

    // epilogue: write partial h for this split
    float* hp = g_hp + (size_t)sp * NH;
#pragma unroll
    for (int mt = 0; mt < 2; ++mt) {
#pragma unroll
        for (int nt = 0; nt < 4; ++nt) {
            int r0 = blockRow + wm * 32 + mt * 16 + g;
            int col = wn * 32 + nt * 8 + tg * 2;
            if (r0 < NN)
                *(float2*)&hp[(size_t)r0 * HID + col] = make_float2(acc[mt][nt][0], acc[mt][nt][1]);
            int r1 = r0 + 8;
            if (r1 < NN)
                *(float2*)&hp[(size_t)r1 * HID + col] = make_float2(acc[mt][nt][2], acc[mt][nt][3]);
        }
    }
}

// ---------------- kernel D2: reduce split-K partials (launch #5) ----------------
__global__ void k_reduce() {
    int i = blockIdx.x * blockDim.x + threadIdx.x;   // float4 index
    const int TOT = NH / 4;                          // 320000
    if (i >= TOT) return;
    const float4* p = (const float4*)g_hp;
    float4 s = p[i];
#pragma unroll
    for (int q = 1; q < SPLITS; ++q) {
        float4 v = p[(size_t)q * TOT + i];
        s.x += v.x; s.y += v.y; s.z += v.z; s.w += v.w;
    }
    ((float4*)g_h)[i] = s;
}

// ---------------- kernel E: dinv + exclusive scan (launch #6) ----------------
__global__ void k_scan() {
    const int PER = 10;
    int t = threadIdx.x;
    int lane = t & 31, w = t >> 5;
#pragma unroll
    for (int p = 0; p < PER; ++p) {
        int idx = t * PER + p;
        if (idx < NN) {
            float d = g_deg[idx];
            g_dinv[idx] = (d > 0.f) ? rsqrtf(d) : 0.f;
        }
    }
    int local[PER];
    int sum = 0;
#pragma unroll
    for (int p = 0; p < PER; ++p) {
        int idx = t * PER + p;
        int v = (idx < NN) ? g_cnt[idx] : 0;
        local[p] = sum;
        sum += v;
    }
    int x = sum;
#pragma unroll
    for (int o = 1; o < 32; o <<= 1) {
        int y = __shfl_up_sync(0xFFFFFFFFu, x, o);
        if (lane >= o) x += y;
    }
    __shared__ int ws[32];
    if (lane == 31) ws[w] = x;
    __syncthreads();
    if (w == 0) {
        int v = ws[lane];
#pragma unroll
        for (int o = 1; o < 32; o <<= 1) {
            int y = __shfl_up_sync(0xFFFFFFFFu, v, o);
            if (lane >= o) v += y;
        }
        ws[lane] = v;
    }
    __syncthreads();
    int base = (x - sum) + (w > 0 ? ws[w - 1] : 0);
#pragma unroll
    for (int p = 0; p < PER; ++p) {
        int idx = t * PER + p;
        if (idx <= NN) g_base[idx] = base + local[p];
    }
}

// ---------------- kernel F: fill CSR buckets (launch #7) ----------------
__global__ void k_fill(const void* __restrict__ ei, const float* __restrict__ ew, int E) {
    int e = blockIdx.x * blockDim.x + threadIdx.x;
    if (e >= E) return;
    int is32 = g_is32;
    int r = load_edge_idx(ei, is32, e);
    int c = load_edge_idx(ei, is32, (long long)E + e);
    float wv = ew[e] * g_dinv[r] * g_dinv[c];
    int pos = atomicAdd(&g_cursor[c], 1);
    g_sr[g_base[c] + pos] = r;
    g_sw[g_base[c] + pos] = wv;
}

// ---------------- kernel G: fused aggregation + bias + ReLU + linear + softmax (launch #8) ----
#define DEG_CAP 192
__global__ void k_agg_final(const float* __restrict__ b_conv,
                            const float* __restrict__ W_lin,
                            const float* __restrict__ b_lin,
                            float* __restrict__ out) {
    __shared__ int   ssr[DEG_CAP];
    __shared__ float ssw[DEG_CAP];
    int i = blockIdx.x;
    int j = threadIdx.x;
    int lane = j & 31, w = j >> 5;

    int s = g_base[i];
    int e2 = g_base[i + 1];
    int deg = e2 - s;
    bool fits = (deg <= DEG_CAP);
    if (fits) {
        for (int p = j; p < deg; p += 128) {
            ssr[p] = g_sr[s + p];
            ssw[p] = g_sw[s + p];
        }
    }
    __syncthreads();

    float di = g_dinv[i];
    float acc0 = g_h[(size_t)i * HID + j] * di * di;
    float acc1 = 0.f;

    if (fits) {
        int p = 0;
        for (; p + 1 < deg; p += 2) {
            acc0 = fmaf(ssw[p],     g_h[(size_t)ssr[p]     * HID + j], acc0);
            acc1 = fmaf(ssw[p + 1], g_h[(size_t)ssr[p + 1] * HID + j], acc1);
        }
        if (p < deg)
            acc0 = fmaf(ssw[p], g_h[(size_t)ssr[p] * HID + j], acc0);
    } else {
        for (int p = s; p < e2; ++p)
            acc0 = fmaf(g_sw[p], g_h[(size_t)g_sr[p] * HID + j], acc0);
    }
    float acc = acc0 + acc1;

    float v = fmaxf(acc + b_conv[j], 0.f);
    float l0 = v * W_lin[j * 2 + 0];
    float l1 = v * W_lin[j * 2 + 1];
#pragma unroll
    for (int o = 16; o > 0; o >>= 1) {
        l0 += __shfl_xor_sync(0xFFFFFFFFu, l0, o);
        l1 += __shfl_xor_sync(0xFFFFFFFFu, l1, o);
    }
    __shared__ float s0[4], s1[4];
    if (lane == 0) { s0[w] = l0; s1[w] = l1; }
    __syncthreads();
    if (j == 0) {
        float L0 = s0[0] + s0[1] + s0[2] + s0[3] + b_lin[0];
        float L1 = s1[0] + s1[1] + s1[2] + s1[3] + b_lin[1];
        float m = fmaxf(L0, L1);
        float e0 = expf(L0 - m), e1 = expf(L1 - m);
        float inv = 1.f / (e0 + e1);
        out[i * 2 + 0] = e0 * inv;
        out[i * 2 + 1] = e1 * inv;
    }
}

// ---------------- launcher ----------------
extern "C" void kernel_launch(void* const* d_in, const int* in_sizes, int n_in,
                              void* d_out, int out_size) {
    const float* x  = (const float*)d_in[0];
    const void*  ei = d_in[1];
    const float* ew = (const float*)d_in[2];
    const float* Wc = (const float*)d_in[3];
    const float* bc = (const float*)d_in[4];
    const float* Wl = (const float*)d_in[5];
    const float* bl = (const float*)d_in[6];
    float*       out = (float*)d_out;
    int E = in_sizes[2];

    int preBlocks = (E + 255) / 256;

    k_transpose<<<dim3((INF + 31) / 32, HID / 32), dim3(32, 32)>>>(Wc);   // 1
    k_pre0<<<preBlocks, 256>>>((const int*)ei, E);                        // 2
    k_count<<<(E + 255) / 256, 256>>>(ei, ew, E);                         // 3

    cudaFuncSetAttribute(k_gemm, cudaFuncAttributeMaxDynamicSharedMemorySize, GEMM_SMEM);
    k_gemm<<<dim3((NN + BM - 1) / BM, SPLITS), 256, GEMM_SMEM>>>(x);      // 4  <-- ncu profiles #4

    k_reduce<<<(NH / 4 + 255) / 256, 256>>>();                            // 5
    k_scan<<<1, 1024>>>();                                                // 6
    k_fill<<<(E + 255) / 256, 256>>>(ei, ew, E);                          // 7
    k_agg_final<<<NN, 128>>>(bc, Wl, bl, out);                            // 8

    (void)n_in; (void)out_size;
}

// round 15
// speedup vs baseline: 1.9754x; 1.0484x over previous
#include <cuda_runtime.h>
#include <cuda_bf16.h>
#include <cstdint>

// Problem constants
#define NN   10000
#define INF  10000
#define HID  128
#define EMAX 320000
#define SPLITS 15
#define NH (NN * HID)

// ---------------- scratch (device globals; no allocation allowed) ----------------
__device__ float g_h[(size_t)NH];                        // h = x @ W_conv (reduced)
__device__ __align__(16) float g_hp[(size_t)SPLITS * NH];// split-K partials (77 MB)
__device__ __align__(16) float g_wt[(size_t)HID * INF];  // W^T [128][10000] (n-major)
__device__ float g_deg[NN];
__device__ float g_dinv[NN];
__device__ int   g_cnt[NN];
__device__ int   g_base[NN + 1];
__device__ int   g_cursor[NN];
__device__ int   g_sr[EMAX];
__device__ float g_sw[EMAX];
__device__ int   g_is32 = 0;   // sticky dtype flag: 1 => edge_index is int32

// ---------------- helpers ----------------
__device__ __forceinline__ unsigned smem_u32(const void* p) {
    unsigned a;
    asm("{ .reg .u64 t; cvta.to.shared.u64 t, %1; cvt.u32.u64 %0, t; }" : "=r"(a) : "l"(p));
    return a;
}

__device__ __forceinline__ void cp_async16(void* smem_dst, const void* gmem_src, int valid_bytes) {
    unsigned saddr = (unsigned)__cvta_generic_to_shared(smem_dst);
    asm volatile("cp.async.cg.shared.global [%0], [%1], 16, %2;\n"
                 :: "r"(saddr), "l"(gmem_src), "r"(valid_bytes));
}

__device__ __forceinline__ int load_edge_idx(const void* ei, int is32, long long pos) {
    if (is32) return ((const int*)ei)[pos];
    return (int)((const long long*)ei)[pos];
}

__device__ __forceinline__ void ldsm4(unsigned r[4], unsigned saddr) {
    asm volatile("ldmatrix.sync.aligned.m8n8.x4.shared.b16 {%0,%1,%2,%3}, [%4];"
                 : "=r"(r[0]), "=r"(r[1]), "=r"(r[2]), "=r"(r[3]) : "r"(saddr));
}

__device__ __forceinline__ void mma_tf32(float c[4], const unsigned a[4], const unsigned b0, const unsigned b1) {
    asm volatile(
        "mma.sync.aligned.m16n8k8.row.col.f32.tf32.tf32.f32 "
        "{%0,%1,%2,%3}, {%4,%5,%6,%7}, {%8,%9}, {%0,%1,%2,%3};\n"
        : "+f"(c[0]), "+f"(c[1]), "+f"(c[2]), "+f"(c[3])
        : "r"(a[0]), "r"(a[1]), "r"(a[2]), "r"(a[3]), "r"(b0), "r"(b1));
}

// ---------------- kernel A: W transpose  W[K][128] -> WT[128][K]  (launch #1) ----------------
__global__ void k_transpose(const float* __restrict__ W) {
    __shared__ float t[32][33];
    int k0 = blockIdx.x * 32, n0 = blockIdx.y * 32;
    int tx = threadIdx.x, ty = threadIdx.y;
    int k = k0 + ty, n = n0 + tx;
    t[ty][tx] = (k < INF) ? W[(size_t)k * HID + n] : 0.f;
    __syncthreads();
    int ko = k0 + tx, no = n0 + ty;
    if (ko < INF) g_wt[(size_t)no * INF + ko] = t[tx][ty];
}

// ---------------- kernel B: init + dtype detect (launch #2) ----------------
__global__ void k_pre0(const int* __restrict__ ei_words, int E) {
    int i = blockIdx.x * blockDim.x + threadIdx.x;
    if (i < NN) {
        g_deg[i] = 1.0f;     // self-loop weight
        g_cnt[i] = 0;
        g_cursor[i] = 0;
    }
    long long idx = 2LL * i + 1;           // odd 32-bit words: zero iff int64
    if (idx < 2LL * E) {
        if (ei_words[idx] != 0) g_is32 = 1;
    }
}

// ---------------- kernel C: degree + count (launch #3) ----------------
__global__ void k_count(const void* __restrict__ ei, const float* __restrict__ ew, int E) {
    int e = blockIdx.x * blockDim.x + threadIdx.x;
    if (e >= E) return;
    int is32 = g_is32;
    int c = load_edge_idx(ei, is32, (long long)E + e);
    atomicAdd(&g_deg[c], ew[e]);
    atomicAdd(&g_cnt[c], 1);
}

// ---------------- kernel D: split-K GEMM with ldmatrix feed (launch #4 -> ncu) ----------
// BM=64, BN=128(full), BK=32, 8 warps (2M x 4N). Identical inner loop to R14.
// ONLY change: SPLITS 4 -> 15 (CPS=21). Grid 2355 = 3.98 x capacity(592) kills the
// 2x scheduling tail (628 = 592+36 forced a second full-length wave on 36 slots).
#define BM 64
#define BK 32
#define NCHUNK 313
#define CPS 21                            // 15*21 = 315 >= 313
#define ASTR 36                           // floats; 144B row stride
#define A_BYTES (BM * ASTR * 4)           // 9216
#define B_BYTES (HID * ASTR * 4)          // 18432
#define STAGE_BYTES (A_BYTES + B_BYTES)   // 27648
#define GEMM_SMEM (2 * STAGE_BYTES)       // 55296 -> occ 4 by smem

__device__ __forceinline__ void gemm_load(char* smem, int stage, int kt,
                                          const float* __restrict__ X,
                                          int blockRow, int tid) {
    char* abase = smem + stage * STAGE_BYTES;
    char* bbase = abase + A_BYTES;
    // A: 64 rows x 32 floats = 512 float4 -> 2 per thread
#pragma unroll
    for (int q = 0; q < 2; ++q) {
        int chunk = tid * 2 + q;
        int row = chunk >> 3;
        int c16 = chunk & 7;
        int col = kt + c16 * 4;
        int grow = blockRow + row;
        int ok = (grow < NN && col < INF) ? 16 : 0;
        const float* src = ok ? (X + (size_t)grow * INF + col) : X;
        cp_async16(abase + (row * ASTR + c16 * 4) * 4, src, ok);
    }
    // B: 128 n-rows x 32 floats = 1024 float4 -> 4 per thread (from g_wt, n-major)
#pragma unroll
    for (int q = 0; q < 4; ++q) {
        int chunk = tid * 4 + q;
        int row = chunk >> 3;
        int c16 = chunk & 7;
        int col = kt + c16 * 4;
        int ok = (col < INF) ? 16 : 0;
        const float* src = ok ? (g_wt + (size_t)row * INF + col) : g_wt;
        cp_async16(bbase + (row * ASTR + c16 * 4) * 4, src, ok);
    }
}

__global__ void __launch_bounds__(256, 4) k_gemm(const float* __restrict__ X) {
    extern __shared__ char smem[];
    unsigned sb = smem_u32(smem);

    int tid = threadIdx.x;
    int lane = tid & 31;
    int wid = tid >> 5;
    int wm = wid & 1;        // 2 warps along M
    int wn = wid >> 1;       // 4 warps along N
    int g = lane >> 2;
    int tg = lane & 3;

    int blockRow = blockIdx.x * BM;
    int sp = blockIdx.y;
    int c0 = sp * CPS;
    int c1 = min(c0 + CPS, NCHUNK);

    // ldmatrix lane offsets (bytes within a stage) — mapping validated in R9/R14
    unsigned aoff[2];
#pragma unroll
    for (int mt = 0; mt < 2; ++mt)
        aoff[mt] = (unsigned)(((wm * 32 + mt * 16 + (lane & 15)) * ASTR + ((lane >> 4) << 2)) * 4);
    unsigned boff[2];
#pragma unroll
    for (int p = 0; p < 2; ++p)
        boff[p] = (unsigned)(((wn * 32 + p * 16 + ((lane >> 4) << 3) + (lane & 7)) * ASTR
                              + (((lane >> 3) & 1) << 2)) * 4) + A_BYTES;

    float acc[2][4][4];
#pragma unroll
    for (int mt = 0; mt < 2; ++mt)
#pragma unroll
        for (int nt = 0; nt < 4; ++nt)
#pragma unroll
            for (int q = 0; q < 4; ++q) acc[mt][nt][q] = 0.f;

    // prologue
    gemm_load(smem, 0, c0 * BK, X, blockRow, tid);
    asm volatile("cp.async.commit_group;\n" ::: "memory");

    for (int t = c0; t < c1; ++t) {
        int buf = (t - c0) & 1;
        if (t + 1 < c1) {
            gemm_load(smem, (t + 1 - c0) & 1, (t + 1) * BK, X, blockRow, tid);
            asm volatile("cp.async.commit_group;\n" ::: "memory");
            asm volatile("cp.async.wait_group 1;\n" ::: "memory");
        } else {
            asm volatile("cp.async.wait_group 0;\n" ::: "memory");
        }
        __syncthreads();

        unsigned sbase = sb + buf * STAGE_BYTES;
#pragma unroll
        for (int ks = 0; ks < 4; ++ks) {
            unsigned kadd = ks * 32;      // 8 floats per k-step
            unsigned A0[4], A1[4], B0[4], B1[4];
            ldsm4(A0, sbase + aoff[0] + kadd);
            ldsm4(A1, sbase + aoff[1] + kadd);
            ldsm4(B0, sbase + boff[0] + kadd);
            ldsm4(B1, sbase + boff[1] + kadd);
            mma_tf32(acc[0][0], A0, B0[0], B0[1]);
            mma_tf32(acc[0][1], A0, B0[2], B0[3]);
            mma_tf32(acc[0][2], A0, B1[0], B1[1]);
            mma_tf32(acc[0][3], A0, B1[2], B1[3]);
            mma_tf32(acc[1][0], A1, B0[0], B0[1]);
            mma_tf32(acc[1][1], A1, B0[2], B0[3]);
            mma_tf32(acc[1][2], A1, B1[0], B1[1]);
            mma_tf32(acc[1][3], A1, B1[2], B1[3]);
        }
        __syncthreads();
    }

    // epilogue: write partial h for this split
    float* hp = g_hp + (size_t)sp * NH;
#pragma unroll
    for (int mt = 0; mt < 2; ++mt) {
#pragma unroll
        for (int nt = 0; nt < 4; ++nt) {
            int r0 = blockRow + wm * 32 + mt * 16 + g;
            int col = wn * 32 + nt * 8 + tg * 2;
            if (r0 < NN)
                *(float2*)&hp[(size_t)r0 * HID + col] = make_float2(acc[mt][nt][0], acc[mt][nt][1]);
            int r1 = r0 + 8;
            if (r1 < NN)
                *(float2*)&hp[(size_t)r1 * HID + col] = make_float2(acc[mt][nt][2], acc[mt][nt][3]);
        }
    }
}

// ---------------- kernel D2: reduce split-K partials (launch #5) ----------------
__global__ void k_reduce() {
    int i = blockIdx.x * blockDim.x + threadIdx.x;   // float4 index
    const int TOT = NH / 4;                          // 320000
    if (i >= TOT) return;
    const float4* p = (const float4*)g_hp;
    float4 s = p[i];
#pragma unroll
    for (int q = 1; q < SPLITS; ++q) {
        float4 v = p[(size_t)q * TOT + i];
        s.x += v.x; s.y += v.y; s.z += v.z; s.w += v.w;
    }
    ((float4*)g_h)[i] = s;
}

// ---------------- kernel E: dinv + exclusive scan (launch #6) ----------------
__global__ void k_scan() {
    const int PER = 10;
    int t = threadIdx.x;
    int lane = t & 31, w = t >> 5;
#pragma unroll
    for (int p = 0; p < PER; ++p) {
        int idx = t * PER + p;
        if (idx < NN) {
            float d = g_deg[idx];
            g_dinv[idx] = (d > 0.f) ? rsqrtf(d) : 0.f;
        }
    }
    int local[PER];
    int sum = 0;
#pragma unroll
    for (int p = 0; p < PER; ++p) {
        int idx = t * PER + p;
        int v = (idx < NN) ? g_cnt[idx] : 0;
        local[p] = sum;
        sum += v;
    }
    int x = sum;
#pragma unroll
    for (int o = 1; o < 32; o <<= 1) {
        int y = __shfl_up_sync(0xFFFFFFFFu, x, o);
        if (lane >= o) x += y;
    }
    __shared__ int ws[32];
    if (lane == 31) ws[w] = x;
    __syncthreads();
    if (w == 0) {
        int v = ws[lane];
#pragma unroll
        for (int o = 1; o < 32; o <<= 1) {
            int y = __shfl_up_sync(0xFFFFFFFFu, v, o);
            if (lane >= o) v += y;
        }
        ws[lane] = v;
    }
    __syncthreads();
    int base = (x - sum) + (w > 0 ? ws[w - 1] : 0);
#pragma unroll
    for (int p = 0; p < PER; ++p) {
        int idx = t * PER + p;
        if (idx <= NN) g_base[idx] = base + local[p];
    }
}

// ---------------- kernel F: fill CSR buckets (launch #7) ----------------
__global__ void k_fill(const void* __restrict__ ei, const float* __restrict__ ew, int E) {
    int e = blockIdx.x * blockDim.x + threadIdx.x;
    if (e >= E) return;
    int is32 = g_is32;
    int r = load_edge_idx(ei, is32, e);
    int c = load_edge_idx(ei, is32, (long long)E + e);
    float wv = ew[e] * g_dinv[r] * g_dinv[c];
    int pos = atomicAdd(&g_cursor[c], 1);
    g_sr[g_base[c] + pos] = r;
    g_sw[g_base[c] + pos] = wv;
}

// ---------------- kernel G: fused aggregation + bias + ReLU + linear + softmax (launch #8) ----
#define DEG_CAP 192
__global__ void k_agg_final(const float* __restrict__ b_conv,
                            const float* __restrict__ W_lin,
                            const float* __restrict__ b_lin,
                            float* __restrict__ out) {
    __shared__ int   ssr[DEG_CAP];
    __shared__ float ssw[DEG_CAP];
    int i = blockIdx.x;
    int j = threadIdx.x;
    int lane = j & 31, w = j >> 5;

    int s = g_base[i];
    int e2 = g_base[i + 1];
    int deg = e2 - s;
    bool fits = (deg <= DEG_CAP);
    if (fits) {
        for (int p = j; p < deg; p += 128) {
            ssr[p] = g_sr[s + p];
            ssw[p] = g_sw[s + p];
        }
    }
    __syncthreads();

    float di = g_dinv[i];
    float acc0 = g_h[(size_t)i * HID + j] * di * di;
    float acc1 = 0.f;

    if (fits) {
        int p = 0;
        for (; p + 1 < deg; p += 2) {
            acc0 = fmaf(ssw[p],     g_h[(size_t)ssr[p]     * HID + j], acc0);
            acc1 = fmaf(ssw[p + 1], g_h[(size_t)ssr[p + 1] * HID + j], acc1);
        }
        if (p < deg)
            acc0 = fmaf(ssw[p], g_h[(size_t)ssr[p] * HID + j], acc0);
    } else {
        for (int p = s; p < e2; ++p)
            acc0 = fmaf(g_sw[p], g_h[(size_t)g_sr[p] * HID + j], acc0);
    }
    float acc = acc0 + acc1;

    float v = fmaxf(acc + b_conv[j], 0.f);
    float l0 = v * W_lin[j * 2 + 0];
    float l1 = v * W_lin[j * 2 + 1];
#pragma unroll
    for (int o = 16; o > 0; o >>= 1) {
        l0 += __shfl_xor_sync(0xFFFFFFFFu, l0, o);
        l1 += __shfl_xor_sync(0xFFFFFFFFu, l1, o);
    }
    __shared__ float s0[4], s1[4];
    if (lane == 0) { s0[w] = l0; s1[w] = l1; }
    __syncthreads();
    if (j == 0) {
        float L0 = s0[0] + s0[1] + s0[2] + s0[3] + b_lin[0];
        float L1 = s1[0] + s1[1] + s1[2] + s1[3] + b_lin[1];
        float m = fmaxf(L0, L1);
        float e0 = expf(L0 - m), e1 = expf(L1 - m);
        float inv = 1.f / (e0 + e1);
        out[i * 2 + 0] = e0 * inv;
        out[i * 2 + 1] = e1 * inv;
    }
}

// ---------------- launcher ----------------
extern "C" void kernel_launch(void* const* d_in, const int* in_sizes, int n_in,
                              void* d_out, int out_size) {
    const float* x  = (const float*)d_in[0];
    const void*  ei = d_in[1];
    const float* ew = (const float*)d_in[2];
    const float* Wc = (const float*)d_in[3];
    const float* bc = (const float*)d_in[4];
    const float* Wl = (const float*)d_in[5];
    const float* bl = (const float*)d_in[6];
    float*       out = (float*)d_out;
    int E = in_sizes[2];

    int preBlocks = (E + 255) / 256;

    k_transpose<<<dim3((INF + 31) / 32, HID / 32), dim3(32, 32)>>>(Wc);   // 1
    k_pre0<<<preBlocks, 256>>>((const int*)ei, E);                        // 2
    k_count<<<(E + 255) / 256, 256>>>(ei, ew, E);                         // 3

    cudaFuncSetAttribute(k_gemm, cudaFuncAttributeMaxDynamicSharedMemorySize, GEMM_SMEM);
    k_gemm<<<dim3((NN + BM - 1) / BM, SPLITS), 256, GEMM_SMEM>>>(x);      // 4  <-- ncu profiles #4

    k_reduce<<<(NH / 4 + 255) / 256, 256>>>();                            // 5
    k_scan<<<1, 1024>>>();                                                // 6
    k_fill<<<(E + 255) / 256, 256>>>(ei, ew, E);                          // 7
    k_agg_final<<<NN, 128>>>(bc, Wl, bl, out);                            // 8

    (void)n_in; (void)out_size;
}